// round 5
// baseline (speedup 1.0000x reference)
#include <cuda_runtime.h>
#include <cuda_fp16.h>

#define N_CELL  60000
#define N_GENE  4000
#define DIM     128
#define E_EDGES 1500000
#define EPS_BN  1e-5f
#define SCAN_B  ((N_CELL + 1023) / 1024)   // 59

#define PADH 136   // half stride for As/Bs (17*8: ldmatrix-aligned)
#define PADF 132   // float stride for Ds
#define MMA_SMEM (2 * 128 * PADH * 2 + 8192)   // As+Bs fp16 (aliased by Ds) + reduce buf

// ---------------- scratch (static __device__, no allocation) ----------------
__device__ int    g_hist[N_CELL];
__device__ int    g_off [N_CELL + 1];
__device__ int    g_cur [N_CELL];
__device__ int    g_bsum[64];
__device__ int    g_boff[64];
__device__ int    g_csr [E_EDGES];
__device__ __half g_y   [(size_t)N_GENE * DIM];   // fp16(x_gene @ Wl)
__device__ float  g_colsum[DIM];
__device__ float  g_colsq [DIM];

// ---------------- 0: zero counters/stats ----------------
__global__ void k_zero() {
    int i = blockIdx.x * blockDim.x + threadIdx.x;
    if (i < N_CELL) g_hist[i] = 0;
    if (i < DIM) { g_colsum[i] = 0.f; g_colsq[i] = 0.f; }
}

// ---------------- 1: histogram of edge destinations (x4 vectorized) ----------------
__global__ void k_hist(const int4* __restrict__ dst) {
    int i = blockIdx.x * blockDim.x + threadIdx.x;
    if (i < E_EDGES / 4) {
        int4 d = __ldg(&dst[i]);
        atomicAdd(&g_hist[d.x], 1);
        atomicAdd(&g_hist[d.y], 1);
        atomicAdd(&g_hist[d.z], 1);
        atomicAdd(&g_hist[d.w], 1);
    }
}

// ---------------- 2a: per-block inclusive scan ----------------
__global__ void k_scan1() {
    __shared__ int wsum[32];
    int t = threadIdx.x, lane = t & 31, wid = t >> 5;
    int i = blockIdx.x * 1024 + t;
    int v = (i < N_CELL) ? g_hist[i] : 0;
    int x = v;
    #pragma unroll
    for (int o = 1; o < 32; o <<= 1) {
        int y = __shfl_up_sync(0xffffffffu, x, o);
        if (lane >= o) x += y;
    }
    if (lane == 31) wsum[wid] = x;
    __syncthreads();
    if (wid == 0) {
        int w = wsum[lane];
        #pragma unroll
        for (int o = 1; o < 32; o <<= 1) {
            int y = __shfl_up_sync(0xffffffffu, w, o);
            if (lane >= o) w += y;
        }
        wsum[lane] = w;
    }
    __syncthreads();
    int incl = x + (wid ? wsum[wid - 1] : 0);
    if (i < N_CELL) g_cur[i] = incl;
    if (t == 1023) g_bsum[blockIdx.x] = incl;
}

// ---------------- 2b: scan the 59 block sums ----------------
__global__ void k_scan2() {
    int t = threadIdx.x, lane = t & 31, wid = t >> 5;  // 64 threads
    __shared__ int w0;
    int v = (t < SCAN_B) ? g_bsum[t] : 0;
    int x = v;
    #pragma unroll
    for (int o = 1; o < 32; o <<= 1) {
        int y = __shfl_up_sync(0xffffffffu, x, o);
        if (lane >= o) x += y;
    }
    if (t == 31) w0 = x;
    __syncthreads();
    int incl = x + (wid ? w0 : 0);
    if (t < SCAN_B) g_boff[t] = incl - v;
}

// ---------------- 2c: finalize offsets + write-cursors ----------------
__global__ void k_scan3() {
    int i = blockIdx.x * blockDim.x + threadIdx.x;
    if (i < N_CELL) {
        int incl = g_cur[i] + g_boff[i >> 10];
        g_off[i + 1] = incl;
        g_cur[i] = incl - g_hist[i];
        if (i == 0) g_off[0] = 0;
    }
}

// ---------------- 3: scatter edge source ids into CSR ----------------
__global__ void k_scatter(const int* __restrict__ src, const int* __restrict__ dst) {
    int i = blockIdx.x * blockDim.x + threadIdx.x;
    if (i < E_EDGES) {
        int d = dst[i];
        int p = atomicAdd(&g_cur[d], 1);
        g_csr[p] = src[i];
    }
}

// ---------------- 4: small fp32 GEMM  g_y = fp16(x_gene @ Wl) ----------------
__global__ __launch_bounds__(256) void k_ygemm(
    const float* __restrict__ A,
    const float* __restrict__ B,
    int M)
{
    __shared__ float As[32][132];
    __shared__ float Bs[32][128];

    int tid = threadIdx.x;
    int tr = tid >> 4, tc = tid & 15;
    int m0 = blockIdx.x * 128;

    float acc[8][8];
    #pragma unroll
    for (int r = 0; r < 8; r++)
        #pragma unroll
        for (int c = 0; c < 8; c++) acc[r][c] = 0.f;

    for (int k0 = 0; k0 < DIM; k0 += 32) {
        #pragma unroll
        for (int t = 0; t < 4; t++) {
            int idx = tid + t * 256;
            int row = idx >> 3, q = idx & 7;
            float4 v = {0.f, 0.f, 0.f, 0.f};
            int gm = m0 + row;
            if (gm < M) v = *(const float4*)&A[(size_t)gm * DIM + k0 + q * 4];
            As[q * 4 + 0][row] = v.x;
            As[q * 4 + 1][row] = v.y;
            As[q * 4 + 2][row] = v.z;
            As[q * 4 + 3][row] = v.w;
        }
        #pragma unroll
        for (int t = 0; t < 4; t++) {
            int idx = tid + t * 256;
            int bk = idx >> 5, bn4 = idx & 31;
            *(float4*)&Bs[bk][bn4 * 4] =
                *(const float4*)&B[(size_t)(k0 + bk) * DIM + bn4 * 4];
        }
        __syncthreads();
        #pragma unroll
        for (int kk = 0; kk < 32; kk++) {
            float a[8], b[8];
            *(float4*)&a[0] = *(const float4*)&As[kk][tr * 8];
            *(float4*)&a[4] = *(const float4*)&As[kk][tr * 8 + 4];
            *(float4*)&b[0] = *(const float4*)&Bs[kk][tc * 8];
            *(float4*)&b[4] = *(const float4*)&Bs[kk][tc * 8 + 4];
            #pragma unroll
            for (int r = 0; r < 8; r++)
                #pragma unroll
                for (int c = 0; c < 8; c++)
                    acc[r][c] += a[r] * b[c];
        }
        __syncthreads();
    }
    #pragma unroll
    for (int r = 0; r < 8; r++) {
        int gm = m0 + tr * 8 + r;
        if (gm < M) {
            #pragma unroll
            for (int c2 = 0; c2 < 4; c2++) {
                __half2 h = __floats2half2_rn(acc[r][c2 * 2], acc[r][c2 * 2 + 1]);
                *(__half2*)&g_y[(size_t)gm * DIM + tc * 8 + c2 * 2] = h;
            }
        }
    }
}

// ---------------- 5: fused  out = mean_gather(g_y) + x_cell@Wr, + BN stats ----------
__device__ __forceinline__ unsigned su32(const void* p) {
    return (unsigned)__cvta_generic_to_shared(p);
}
__device__ __forceinline__ void ldsm4(unsigned a, unsigned& r0, unsigned& r1,
                                      unsigned& r2, unsigned& r3) {
    asm volatile("ldmatrix.sync.aligned.m8n8.x4.shared.b16 {%0,%1,%2,%3}, [%4];"
                 : "=r"(r0), "=r"(r1), "=r"(r2), "=r"(r3) : "r"(a));
}
__device__ __forceinline__ void ldsm4t(unsigned a, unsigned& r0, unsigned& r1,
                                       unsigned& r2, unsigned& r3) {
    asm volatile("ldmatrix.sync.aligned.m8n8.x4.trans.shared.b16 {%0,%1,%2,%3}, [%4];"
                 : "=r"(r0), "=r"(r1), "=r"(r2), "=r"(r3) : "r"(a));
}
__device__ __forceinline__ void mma16816(float* d, const unsigned* a, const unsigned* b) {
    asm volatile(
        "mma.sync.aligned.m16n8k16.row.col.f32.f16.f16.f32 "
        "{%0,%1,%2,%3}, {%4,%5,%6,%7}, {%8,%9}, {%0,%1,%2,%3};"
        : "+f"(d[0]), "+f"(d[1]), "+f"(d[2]), "+f"(d[3])
        : "r"(a[0]), "r"(a[1]), "r"(a[2]), "r"(a[3]), "r"(b[0]), "r"(b[1]));
}

__global__ __launch_bounds__(256, 2) void k_fused(
    const float* __restrict__ x_cell,
    const float* __restrict__ Wr,
    float* __restrict__ out,
    int M)
{
    extern __shared__ char smem[];
    __half* As = (__half*)smem;                        // [128][PADH]
    __half* Bs = (__half*)smem + 128 * PADH;           // [128][PADH], stored [k][n]
    float*  Ds = (float*)smem;                         // [128][PADF] (aliases As/Bs)
    float*  red = (float*)(smem + 2 * 128 * PADH * 2); // 2048 floats

    int tid  = threadIdx.x;
    int warp = tid >> 5, lane = tid & 31;
    int wm = warp & 3, wn = warp >> 2;   // 4 x 2 warp grid; warp tile 32m x 64n
    int m0 = blockIdx.x * 128;

    // load A tile (fp32 -> fp16)
    #pragma unroll
    for (int it = 0; it < 16; it++) {
        int idx = tid + it * 256;
        int row = idx >> 5, q = idx & 31;
        float4 v = {0.f, 0.f, 0.f, 0.f};
        int gm = m0 + row;
        if (gm < M) v = *(const float4*)&x_cell[(size_t)gm * DIM + q * 4];
        *(__half2*)&As[row * PADH + q * 4]     = __floats2half2_rn(v.x, v.y);
        *(__half2*)&As[row * PADH + q * 4 + 2] = __floats2half2_rn(v.z, v.w);
    }
    // load B tile [k][n] (fp32 -> fp16)
    #pragma unroll
    for (int it = 0; it < 16; it++) {
        int idx = tid + it * 256;
        int k = idx >> 5, n4 = idx & 31;
        float4 v = *(const float4*)&Wr[(size_t)k * DIM + n4 * 4];
        *(__half2*)&Bs[k * PADH + n4 * 4]     = __floats2half2_rn(v.x, v.y);
        *(__half2*)&Bs[k * PADH + n4 * 4 + 2] = __floats2half2_rn(v.z, v.w);
    }
    __syncthreads();

    float acc[2][8][4];
    #pragma unroll
    for (int tm = 0; tm < 2; tm++)
        #pragma unroll
        for (int tn = 0; tn < 8; tn++)
            #pragma unroll
            for (int j = 0; j < 4; j++) acc[tm][tn][j] = 0.f;

    #pragma unroll
    for (int ks = 0; ks < 8; ks++) {
        unsigned a[2][4], b[8][2];
        #pragma unroll
        for (int tm = 0; tm < 2; tm++) {
            unsigned addr = su32(&As[(wm * 32 + tm * 16 + (lane & 15)) * PADH
                                     + ks * 16 + (lane >> 4) * 8]);
            ldsm4(addr, a[tm][0], a[tm][1], a[tm][2], a[tm][3]);
        }
        #pragma unroll
        for (int tp = 0; tp < 4; tp++) {
            unsigned addr = su32(&Bs[(ks * 16 + (lane & 15)) * PADH
                                     + wn * 64 + tp * 16 + (lane >> 4) * 8]);
            ldsm4t(addr, b[tp * 2][0], b[tp * 2][1], b[tp * 2 + 1][0], b[tp * 2 + 1][1]);
        }
        #pragma unroll
        for (int tm = 0; tm < 2; tm++)
            #pragma unroll
            for (int tn = 0; tn < 8; tn++)
                mma16816(acc[tm][tn], a[tm], b[tn]);
    }

    __syncthreads();   // done reading As/Bs; reuse as Ds
    #pragma unroll
    for (int tm = 0; tm < 2; tm++) {
        int r0 = wm * 32 + tm * 16 + (lane >> 2);
        #pragma unroll
        for (int tn = 0; tn < 8; tn++) {
            int c = wn * 64 + tn * 8 + (lane & 3) * 2;
            *(float2*)&Ds[r0 * PADF + c]       = make_float2(acc[tm][tn][0], acc[tm][tn][1]);
            *(float2*)&Ds[(r0 + 8) * PADF + c] = make_float2(acc[tm][tn][2], acc[tm][tn][3]);
        }
    }
    __syncthreads();

    // fused epilogue: warp w handles rows w*16..w*16+15.
    // For each row: warp-parallel neighbor-mean gather from fp16 g_y, add GEMM
    // result, store, accumulate per-column BN partial stats.
    const uint2* yv = (const uint2*)g_y;   // 4 halves per lane per gene row
    float s[4] = {0.f, 0.f, 0.f, 0.f};
    float q[4] = {0.f, 0.f, 0.f, 0.f};
    int rb = warp * 16;

    for (int i = 0; i < 16; i++) {
        int r = rb + i, gm = m0 + r;
        if (gm >= M) break;
        int es = g_off[gm], ee = g_off[gm + 1];

        float ax0=0.f, ax1=0.f, ax2=0.f, ax3=0.f;
        float bx0=0.f, bx1=0.f, bx2=0.f, bx3=0.f;
        float cx0=0.f, cx1=0.f, cx2=0.f, cx3=0.f;
        float dx0=0.f, dx1=0.f, dx2=0.f, dx3=0.f;
        int j = es;
        for (; j + 3 < ee; j += 4) {
            int g0 = __ldg(&g_csr[j]);
            int g1 = __ldg(&g_csr[j + 1]);
            int g2 = __ldg(&g_csr[j + 2]);
            int g3 = __ldg(&g_csr[j + 3]);
            uint2 u0 = __ldg(&yv[(size_t)g0 * 32 + lane]);
            uint2 u1 = __ldg(&yv[(size_t)g1 * 32 + lane]);
            uint2 u2 = __ldg(&yv[(size_t)g2 * 32 + lane]);
            uint2 u3 = __ldg(&yv[(size_t)g3 * 32 + lane]);
            float2 p0, q0;
            p0 = __half22float2(*(__half2*)&u0.x); q0 = __half22float2(*(__half2*)&u0.y);
            ax0 += p0.x; ax1 += p0.y; ax2 += q0.x; ax3 += q0.y;
            p0 = __half22float2(*(__half2*)&u1.x); q0 = __half22float2(*(__half2*)&u1.y);
            bx0 += p0.x; bx1 += p0.y; bx2 += q0.x; bx3 += q0.y;
            p0 = __half22float2(*(__half2*)&u2.x); q0 = __half22float2(*(__half2*)&u2.y);
            cx0 += p0.x; cx1 += p0.y; cx2 += q0.x; cx3 += q0.y;
            p0 = __half22float2(*(__half2*)&u3.x); q0 = __half22float2(*(__half2*)&u3.y);
            dx0 += p0.x; dx1 += p0.y; dx2 += q0.x; dx3 += q0.y;
        }
        for (; j < ee; j++) {
            int g0 = __ldg(&g_csr[j]);
            uint2 u0 = __ldg(&yv[(size_t)g0 * 32 + lane]);
            float2 p0 = __half22float2(*(__half2*)&u0.x);
            float2 q0 = __half22float2(*(__half2*)&u0.y);
            ax0 += p0.x; ax1 += p0.y; ax2 += q0.x; ax3 += q0.y;
        }
        float inv = 1.f / (float)max(ee - es, 1);
        float4 v = *(float4*)&Ds[r * PADF + lane * 4];
        v.x = fmaf(ax0 + bx0 + cx0 + dx0, inv, v.x);
        v.y = fmaf(ax1 + bx1 + cx1 + dx1, inv, v.y);
        v.z = fmaf(ax2 + bx2 + cx2 + dx2, inv, v.z);
        v.w = fmaf(ax3 + bx3 + cx3 + dx3, inv, v.w);
        *(float4*)&out[(size_t)gm * DIM + lane * 4] = v;
        s[0] += v.x; q[0] += v.x * v.x;
        s[1] += v.y; q[1] += v.y * v.y;
        s[2] += v.z; q[2] += v.z * v.z;
        s[3] += v.w; q[3] += v.w * v.w;
    }

    __syncthreads();   // all Ds reads done before red writes (red is separate region)
    #pragma unroll
    for (int c = 0; c < 4; c++) {
        red[warp * DIM + lane * 4 + c]        = s[c];
        red[1024 + warp * DIM + lane * 4 + c] = q[c];
    }
    __syncthreads();
    if (tid < DIM) {
        float ss = 0.f, qq = 0.f;
        #pragma unroll
        for (int r = 0; r < 8; r++) {
            ss += red[r * DIM + tid];
            qq += red[1024 + r * DIM + tid];
        }
        atomicAdd(&g_colsum[tid], ss);
        atomicAdd(&g_colsq[tid], qq);
    }
}

// ---------------- 6: normalize in place (BN stats finalized inline) ----------------
__global__ void k_norm(float* __restrict__ out) {
    int i = blockIdx.x * blockDim.x + threadIdx.x;   // float4 index
    const int total = N_CELL * DIM / 4;
    if (i < total) {
        int c = (i & 31) * 4;
        const float invN = 1.f / (float)N_CELL;
        float mu0 = g_colsum[c + 0] * invN, mu1 = g_colsum[c + 1] * invN;
        float mu2 = g_colsum[c + 2] * invN, mu3 = g_colsum[c + 3] * invN;
        float rs0 = rsqrtf(g_colsq[c + 0] * invN - mu0 * mu0 + EPS_BN);
        float rs1 = rsqrtf(g_colsq[c + 1] * invN - mu1 * mu1 + EPS_BN);
        float rs2 = rsqrtf(g_colsq[c + 2] * invN - mu2 * mu2 + EPS_BN);
        float rs3 = rsqrtf(g_colsq[c + 3] * invN - mu3 * mu3 + EPS_BN);
        float4 v = ((float4*)out)[i];
        v.x = (v.x - mu0) * rs0;
        v.y = (v.y - mu1) * rs1;
        v.z = (v.z - mu2) * rs2;
        v.w = (v.w - mu3) * rs3;
        ((float4*)out)[i] = v;
    }
}

// ---------------- launch ----------------
extern "C" void kernel_launch(void* const* d_in, const int* in_sizes, int n_in,
                              void* d_out, int out_size) {
    const float* x_cell = (const float*)d_in[0];
    const float* x_gene = (const float*)d_in[1];
    const float* Wl_gc  = (const float*)d_in[2];
    const float* Wr_gc  = (const float*)d_in[4];
    const int* gc_src = (const int*)d_in[8];
    const int* gc_dst = (const int*)d_in[9];
    float* out = (float*)d_out;

    const float* Wl = Wl_gc + DIM * DIM;   // layer L-1 = 1
    const float* Wr = Wr_gc + DIM * DIM;

    static bool attr_set = false;
    if (!attr_set) {
        cudaFuncSetAttribute(k_fused, cudaFuncAttributeMaxDynamicSharedMemorySize, MMA_SMEM);
        attr_set = true;
    }

    k_zero   <<<(N_CELL + 255) / 256, 256>>>();
    k_hist   <<<(E_EDGES / 4 + 255) / 256, 256>>>((const int4*)gc_dst);
    k_scan1  <<<SCAN_B, 1024>>>();
    k_scan2  <<<1, 64>>>();
    k_scan3  <<<(N_CELL + 255) / 256, 256>>>();
    k_scatter<<<(E_EDGES + 255) / 256, 256>>>(gc_src, gc_dst);
    k_ygemm  <<<(N_GENE + 127) / 128, 256>>>(x_gene, Wl, N_GENE);
    k_fused  <<<(N_CELL + 127) / 128, 256, MMA_SMEM>>>(x_cell, Wr, out, N_CELL);
    k_norm   <<<(N_CELL * DIM / 4 + 255) / 256, 256>>>(out);
}

// round 7
// speedup vs baseline: 1.1979x; 1.1979x over previous
#include <cuda_runtime.h>
#include <cuda_fp16.h>

#define N_CELL  60000
#define N_GENE  4000
#define DIM     128
#define E_EDGES 1500000
#define EPS_BN  1e-5f
#define SCAN_B  ((N_CELL + 1023) / 1024)   // 59

#define PADH 136   // half stride for As/Bs (17*8: ldmatrix-aligned)
#define GEMM_SMEM (2 * 128 * PADH * 2)     // As+Bs fp16

#define CPW 8      // cells per warp in k_aggbn

// ---------------- scratch (static __device__, no allocation) ----------------
__device__ int    g_hist[N_CELL];
__device__ int    g_off [N_CELL + 1];
__device__ int    g_cur [N_CELL];
__device__ int    g_bsum[64];
__device__ int    g_boff[64];
__device__ int    g_csr [E_EDGES];
__device__ __half g_y   [(size_t)N_GENE * DIM];   // fp16(x_gene @ Wl)
__device__ float  g_colsum[DIM];
__device__ float  g_colsq [DIM];

// ---------------- 0: zero counters/stats ----------------
__global__ void k_zero() {
    int i = blockIdx.x * blockDim.x + threadIdx.x;
    if (i < N_CELL) g_hist[i] = 0;
    if (i < DIM) { g_colsum[i] = 0.f; g_colsq[i] = 0.f; }
}

// ---------------- 1: histogram of edge destinations (x4 vectorized) ----------------
__global__ void k_hist(const int4* __restrict__ dst) {
    int i = blockIdx.x * blockDim.x + threadIdx.x;
    if (i < E_EDGES / 4) {
        int4 d = __ldg(&dst[i]);
        atomicAdd(&g_hist[d.x], 1);
        atomicAdd(&g_hist[d.y], 1);
        atomicAdd(&g_hist[d.z], 1);
        atomicAdd(&g_hist[d.w], 1);
    }
}

// ---------------- 2a: per-block inclusive scan ----------------
__global__ void k_scan1() {
    __shared__ int wsum[32];
    int t = threadIdx.x, lane = t & 31, wid = t >> 5;
    int i = blockIdx.x * 1024 + t;
    int v = (i < N_CELL) ? g_hist[i] : 0;
    int x = v;
    #pragma unroll
    for (int o = 1; o < 32; o <<= 1) {
        int y = __shfl_up_sync(0xffffffffu, x, o);
        if (lane >= o) x += y;
    }
    if (lane == 31) wsum[wid] = x;
    __syncthreads();
    if (wid == 0) {
        int w = wsum[lane];
        #pragma unroll
        for (int o = 1; o < 32; o <<= 1) {
            int y = __shfl_up_sync(0xffffffffu, w, o);
            if (lane >= o) w += y;
        }
        wsum[lane] = w;
    }
    __syncthreads();
    int incl = x + (wid ? wsum[wid - 1] : 0);
    if (i < N_CELL) g_cur[i] = incl;
    if (t == 1023) g_bsum[blockIdx.x] = incl;
}

// ---------------- 2b: scan the 59 block sums ----------------
__global__ void k_scan2() {
    int t = threadIdx.x, lane = t & 31, wid = t >> 5;  // 64 threads
    __shared__ int w0;
    int v = (t < SCAN_B) ? g_bsum[t] : 0;
    int x = v;
    #pragma unroll
    for (int o = 1; o < 32; o <<= 1) {
        int y = __shfl_up_sync(0xffffffffu, x, o);
        if (lane >= o) x += y;
    }
    if (t == 31) w0 = x;
    __syncthreads();
    int incl = x + (wid ? w0 : 0);
    if (t < SCAN_B) g_boff[t] = incl - v;
}

// ---------------- 2c: finalize offsets + write-cursors ----------------
__global__ void k_scan3() {
    int i = blockIdx.x * blockDim.x + threadIdx.x;
    if (i < N_CELL) {
        int incl = g_cur[i] + g_boff[i >> 10];
        g_off[i + 1] = incl;
        g_cur[i] = incl - g_hist[i];
        if (i == 0) g_off[0] = 0;
    }
}

// ---------------- 3: scatter edges into CSR (4 edges / thread for MLP) -------------
__global__ void k_scatter(const int4* __restrict__ src, const int4* __restrict__ dst) {
    int i = blockIdx.x * blockDim.x + threadIdx.x;
    if (i < E_EDGES / 4) {
        int4 s = __ldg(&src[i]);
        int4 d = __ldg(&dst[i]);
        int p0 = atomicAdd(&g_cur[d.x], 1);
        int p1 = atomicAdd(&g_cur[d.y], 1);
        int p2 = atomicAdd(&g_cur[d.z], 1);
        int p3 = atomicAdd(&g_cur[d.w], 1);
        g_csr[p0] = s.x;
        g_csr[p1] = s.y;
        g_csr[p2] = s.z;
        g_csr[p3] = s.w;
    }
}

// ---------------- 4: small fp32 GEMM  g_y = fp16(x_gene @ Wl) ----------------
__global__ __launch_bounds__(256) void k_ygemm(
    const float* __restrict__ A,
    const float* __restrict__ B,
    int M)
{
    __shared__ float As[32][132];
    __shared__ float Bs[32][128];

    int tid = threadIdx.x;
    int tr = tid >> 4, tc = tid & 15;
    int m0 = blockIdx.x * 128;

    float acc[8][8];
    #pragma unroll
    for (int r = 0; r < 8; r++)
        #pragma unroll
        for (int c = 0; c < 8; c++) acc[r][c] = 0.f;

    for (int k0 = 0; k0 < DIM; k0 += 32) {
        #pragma unroll
        for (int t = 0; t < 4; t++) {
            int idx = tid + t * 256;
            int row = idx >> 3, q = idx & 7;
            float4 v = {0.f, 0.f, 0.f, 0.f};
            int gm = m0 + row;
            if (gm < M) v = *(const float4*)&A[(size_t)gm * DIM + k0 + q * 4];
            As[q * 4 + 0][row] = v.x;
            As[q * 4 + 1][row] = v.y;
            As[q * 4 + 2][row] = v.z;
            As[q * 4 + 3][row] = v.w;
        }
        #pragma unroll
        for (int t = 0; t < 4; t++) {
            int idx = tid + t * 256;
            int bk = idx >> 5, bn4 = idx & 31;
            *(float4*)&Bs[bk][bn4 * 4] =
                *(const float4*)&B[(size_t)(k0 + bk) * DIM + bn4 * 4];
        }
        __syncthreads();
        #pragma unroll
        for (int kk = 0; kk < 32; kk++) {
            float a[8], b[8];
            *(float4*)&a[0] = *(const float4*)&As[kk][tr * 8];
            *(float4*)&a[4] = *(const float4*)&As[kk][tr * 8 + 4];
            *(float4*)&b[0] = *(const float4*)&Bs[kk][tc * 8];
            *(float4*)&b[4] = *(const float4*)&Bs[kk][tc * 8 + 4];
            #pragma unroll
            for (int r = 0; r < 8; r++)
                #pragma unroll
                for (int c = 0; c < 8; c++)
                    acc[r][c] += a[r] * b[c];
        }
        __syncthreads();
    }
    #pragma unroll
    for (int r = 0; r < 8; r++) {
        int gm = m0 + tr * 8 + r;
        if (gm < M) {
            #pragma unroll
            for (int c2 = 0; c2 < 4; c2++) {
                __half2 h = __floats2half2_rn(acc[r][c2 * 2], acc[r][c2 * 2 + 1]);
                *(__half2*)&g_y[(size_t)gm * DIM + tc * 8 + c2 * 2] = h;
            }
        }
    }
}

// ---------------- 5: tensor-core GEMM  out = x_cell @ Wr (direct store) -----------
__device__ __forceinline__ unsigned su32(const void* p) {
    return (unsigned)__cvta_generic_to_shared(p);
}
__device__ __forceinline__ void ldsm4(unsigned a, unsigned& r0, unsigned& r1,
                                      unsigned& r2, unsigned& r3) {
    asm volatile("ldmatrix.sync.aligned.m8n8.x4.shared.b16 {%0,%1,%2,%3}, [%4];"
                 : "=r"(r0), "=r"(r1), "=r"(r2), "=r"(r3) : "r"(a));
}
__device__ __forceinline__ void ldsm4t(unsigned a, unsigned& r0, unsigned& r1,
                                       unsigned& r2, unsigned& r3) {
    asm volatile("ldmatrix.sync.aligned.m8n8.x4.trans.shared.b16 {%0,%1,%2,%3}, [%4];"
                 : "=r"(r0), "=r"(r1), "=r"(r2), "=r"(r3) : "r"(a));
}
__device__ __forceinline__ void mma16816(float* d, const unsigned* a, const unsigned* b) {
    asm volatile(
        "mma.sync.aligned.m16n8k16.row.col.f32.f16.f16.f32 "
        "{%0,%1,%2,%3}, {%4,%5,%6,%7}, {%8,%9}, {%0,%1,%2,%3};"
        : "+f"(d[0]), "+f"(d[1]), "+f"(d[2]), "+f"(d[3])
        : "r"(a[0]), "r"(a[1]), "r"(a[2]), "r"(a[3]), "r"(b[0]), "r"(b[1]));
}

__global__ __launch_bounds__(256, 2) void k_gemm_direct(
    const float* __restrict__ x_cell,
    const float* __restrict__ Wr,
    float* __restrict__ out,
    int M)
{
    extern __shared__ char smem[];
    __half* As = (__half*)smem;                // [128][PADH]
    __half* Bs = (__half*)smem + 128 * PADH;   // [128][PADH], stored [k][n]

    int tid  = threadIdx.x;
    int warp = tid >> 5, lane = tid & 31;
    int wm = warp & 3, wn = warp >> 2;   // 4 x 2 warp grid; warp tile 32m x 64n
    int m0 = blockIdx.x * 128;

    // load A tile (fp32 -> fp16)
    #pragma unroll
    for (int it = 0; it < 16; it++) {
        int idx = tid + it * 256;
        int row = idx >> 5, q = idx & 31;
        float4 v = {0.f, 0.f, 0.f, 0.f};
        int gm = m0 + row;
        if (gm < M) v = *(const float4*)&x_cell[(size_t)gm * DIM + q * 4];
        *(__half2*)&As[row * PADH + q * 4]     = __floats2half2_rn(v.x, v.y);
        *(__half2*)&As[row * PADH + q * 4 + 2] = __floats2half2_rn(v.z, v.w);
    }
    // load B tile [k][n] (fp32 -> fp16)
    #pragma unroll
    for (int it = 0; it < 16; it++) {
        int idx = tid + it * 256;
        int k = idx >> 5, n4 = idx & 31;
        float4 v = *(const float4*)&Wr[(size_t)k * DIM + n4 * 4];
        *(__half2*)&Bs[k * PADH + n4 * 4]     = __floats2half2_rn(v.x, v.y);
        *(__half2*)&Bs[k * PADH + n4 * 4 + 2] = __floats2half2_rn(v.z, v.w);
    }
    __syncthreads();

    float acc[2][8][4];
    #pragma unroll
    for (int tm = 0; tm < 2; tm++)
        #pragma unroll
        for (int tn = 0; tn < 8; tn++)
            #pragma unroll
            for (int j = 0; j < 4; j++) acc[tm][tn][j] = 0.f;

    #pragma unroll
    for (int ks = 0; ks < 8; ks++) {
        unsigned a[2][4], b[8][2];
        #pragma unroll
        for (int tm = 0; tm < 2; tm++) {
            unsigned addr = su32(&As[(wm * 32 + tm * 16 + (lane & 15)) * PADH
                                     + ks * 16 + (lane >> 4) * 8]);
            ldsm4(addr, a[tm][0], a[tm][1], a[tm][2], a[tm][3]);
        }
        #pragma unroll
        for (int tp = 0; tp < 4; tp++) {
            unsigned addr = su32(&Bs[(ks * 16 + (lane & 15)) * PADH
                                     + wn * 64 + tp * 16 + (lane >> 4) * 8]);
            ldsm4t(addr, b[tp * 2][0], b[tp * 2][1], b[tp * 2 + 1][0], b[tp * 2 + 1][1]);
        }
        #pragma unroll
        for (int tm = 0; tm < 2; tm++)
            #pragma unroll
            for (int tn = 0; tn < 8; tn++)
                mma16816(acc[tm][tn], a[tm], b[tn]);
    }

    // direct fragment store to out (no epilogue work here)
    #pragma unroll
    for (int tm = 0; tm < 2; tm++) {
        int r0 = m0 + wm * 32 + tm * 16 + (lane >> 2);
        #pragma unroll
        for (int tn = 0; tn < 8; tn++) {
            int c = wn * 64 + tn * 8 + (lane & 3) * 2;
            if (r0 < M)
                *(float2*)&out[(size_t)r0 * DIM + c] =
                    make_float2(acc[tm][tn][0], acc[tm][tn][1]);
            if (r0 + 8 < M)
                *(float2*)&out[(size_t)(r0 + 8) * DIM + c] =
                    make_float2(acc[tm][tn][2], acc[tm][tn][3]);
        }
    }
}

// ---------------- 6: gather-mean + add into out + BN stats (high occupancy) --------
__global__ __launch_bounds__(256) void k_aggbn(float* __restrict__ out) {
    __shared__ float red[2][8][DIM];
    int tid  = threadIdx.x;
    int warp = tid >> 5, lane = tid & 31;
    const uint2* yv = (const uint2*)g_y;   // 4 halves per lane per gene row

    float s[4] = {0.f, 0.f, 0.f, 0.f};
    float q[4] = {0.f, 0.f, 0.f, 0.f};
    int cell0 = (blockIdx.x * 8 + warp) * CPW;

    for (int ci = 0; ci < CPW; ci++) {
        int gm = cell0 + ci;
        if (gm >= N_CELL) break;
        int es = g_off[gm], ee = g_off[gm + 1];

        float ax0=0.f, ax1=0.f, ax2=0.f, ax3=0.f;
        float bx0=0.f, bx1=0.f, bx2=0.f, bx3=0.f;
        float cx0=0.f, cx1=0.f, cx2=0.f, cx3=0.f;
        float dx0=0.f, dx1=0.f, dx2=0.f, dx3=0.f;
        int j = es;
        for (; j + 3 < ee; j += 4) {
            int g0 = __ldg(&g_csr[j]);
            int g1 = __ldg(&g_csr[j + 1]);
            int g2 = __ldg(&g_csr[j + 2]);
            int g3 = __ldg(&g_csr[j + 3]);
            uint2 u0 = __ldg(&yv[(size_t)g0 * 32 + lane]);
            uint2 u1 = __ldg(&yv[(size_t)g1 * 32 + lane]);
            uint2 u2 = __ldg(&yv[(size_t)g2 * 32 + lane]);
            uint2 u3 = __ldg(&yv[(size_t)g3 * 32 + lane]);
            float2 p0, q0;
            p0 = __half22float2(*(__half2*)&u0.x); q0 = __half22float2(*(__half2*)&u0.y);
            ax0 += p0.x; ax1 += p0.y; ax2 += q0.x; ax3 += q0.y;
            p0 = __half22float2(*(__half2*)&u1.x); q0 = __half22float2(*(__half2*)&u1.y);
            bx0 += p0.x; bx1 += p0.y; bx2 += q0.x; bx3 += q0.y;
            p0 = __half22float2(*(__half2*)&u2.x); q0 = __half22float2(*(__half2*)&u2.y);
            cx0 += p0.x; cx1 += p0.y; cx2 += q0.x; cx3 += q0.y;
            p0 = __half22float2(*(__half2*)&u3.x); q0 = __half22float2(*(__half2*)&u3.y);
            dx0 += p0.x; dx1 += p0.y; dx2 += q0.x; dx3 += q0.y;
        }
        for (; j < ee; j++) {
            int g0 = __ldg(&g_csr[j]);
            uint2 u0 = __ldg(&yv[(size_t)g0 * 32 + lane]);
            float2 p0 = __half22float2(*(__half2*)&u0.x);
            float2 q0 = __half22float2(*(__half2*)&u0.y);
            ax0 += p0.x; ax1 += p0.y; ax2 += q0.x; ax3 += q0.y;
        }
        float inv = 1.f / (float)max(ee - es, 1);
        float4 v = *(float4*)&out[(size_t)gm * DIM + lane * 4];
        v.x = fmaf(ax0 + bx0 + cx0 + dx0, inv, v.x);
        v.y = fmaf(ax1 + bx1 + cx1 + dx1, inv, v.y);
        v.z = fmaf(ax2 + bx2 + cx2 + dx2, inv, v.z);
        v.w = fmaf(ax3 + bx3 + cx3 + dx3, inv, v.w);
        *(float4*)&out[(size_t)gm * DIM + lane * 4] = v;
        s[0] += v.x; q[0] += v.x * v.x;
        s[1] += v.y; q[1] += v.y * v.y;
        s[2] += v.z; q[2] += v.z * v.z;
        s[3] += v.w; q[3] += v.w * v.w;
    }

    // block-reduce BN partials, one atomic per column per block
    #pragma unroll
    for (int c = 0; c < 4; c++) {
        red[0][warp][lane * 4 + c] = s[c];
        red[1][warp][lane * 4 + c] = q[c];
    }
    __syncthreads();
    if (tid < DIM) {
        float ss = 0.f, qq = 0.f;
        #pragma unroll
        for (int r = 0; r < 8; r++) { ss += red[0][r][tid]; qq += red[1][r][tid]; }
        atomicAdd(&g_colsum[tid], ss);
        atomicAdd(&g_colsq[tid], qq);
    }
}

// ---------------- 7: normalize in place (BN stats finalized inline) ----------------
__global__ void k_norm(float* __restrict__ out) {
    int i = blockIdx.x * blockDim.x + threadIdx.x;   // float4 index
    const int total = N_CELL * DIM / 4;
    if (i < total) {
        int c = (i & 31) * 4;
        const float invN = 1.f / (float)N_CELL;
        float mu0 = g_colsum[c + 0] * invN, mu1 = g_colsum[c + 1] * invN;
        float mu2 = g_colsum[c + 2] * invN, mu3 = g_colsum[c + 3] * invN;
        float rs0 = rsqrtf(g_colsq[c + 0] * invN - mu0 * mu0 + EPS_BN);
        float rs1 = rsqrtf(g_colsq[c + 1] * invN - mu1 * mu1 + EPS_BN);
        float rs2 = rsqrtf(g_colsq[c + 2] * invN - mu2 * mu2 + EPS_BN);
        float rs3 = rsqrtf(g_colsq[c + 3] * invN - mu3 * mu3 + EPS_BN);
        float4 v = ((float4*)out)[i];
        v.x = (v.x - mu0) * rs0;
        v.y = (v.y - mu1) * rs1;
        v.z = (v.z - mu2) * rs2;
        v.w = (v.w - mu3) * rs3;
        ((float4*)out)[i] = v;
    }
}

// ---------------- launch (single stream — capture-safe) ----------------
extern "C" void kernel_launch(void* const* d_in, const int* in_sizes, int n_in,
                              void* d_out, int out_size) {
    const float* x_cell = (const float*)d_in[0];
    const float* x_gene = (const float*)d_in[1];
    const float* Wl_gc  = (const float*)d_in[2];
    const float* Wr_gc  = (const float*)d_in[4];
    const int* gc_src = (const int*)d_in[8];
    const int* gc_dst = (const int*)d_in[9];
    float* out = (float*)d_out;

    const float* Wl = Wl_gc + DIM * DIM;   // layer L-1 = 1
    const float* Wr = Wr_gc + DIM * DIM;

    static bool attr_set = false;
    if (!attr_set) {
        cudaFuncSetAttribute(k_gemm_direct,
                             cudaFuncAttributeMaxDynamicSharedMemorySize, GEMM_SMEM);
        attr_set = true;
    }

    k_zero   <<<(N_CELL + 255) / 256, 256>>>();
    k_hist   <<<(E_EDGES / 4 + 255) / 256, 256>>>((const int4*)gc_dst);
    k_scan1  <<<SCAN_B, 1024>>>();
    k_scan2  <<<1, 64>>>();
    k_scan3  <<<(N_CELL + 255) / 256, 256>>>();
    k_scatter<<<(E_EDGES / 4 + 255) / 256, 256>>>(
        (const int4*)gc_src, (const int4*)gc_dst);
    k_ygemm  <<<(N_GENE + 127) / 128, 256>>>(x_gene, Wl, N_GENE);
    k_gemm_direct<<<(N_CELL + 127) / 128, 256, GEMM_SMEM>>>(x_cell, Wr, out, N_CELL);
    k_aggbn  <<<(N_CELL + 8 * CPW - 1) / (8 * CPW), 256>>>(out);
    k_norm   <<<(N_CELL * DIM / 4 + 255) / 256, 256>>>(out);
}

// round 8
// speedup vs baseline: 1.3375x; 1.1166x over previous
#include <cuda_runtime.h>
#include <cuda_fp16.h>

#define N_CELL  60000
#define N_GENE  4000
#define DIM     128
#define E_EDGES 1500000
#define EPS_BN  1e-5f
#define SCAN_B  ((N_CELL + 1023) / 1024)   // 59

#define PADH 136   // half stride for As/Bs (17*8: ldmatrix-aligned)
#define GEMM_SMEM (2 * 128 * PADH * 2)     // As+Bs fp16

#define CPW 8      // cells per warp in k_aggbn

// ---------------- scratch (static __device__, no allocation) ----------------
__device__ int    g_hist[N_CELL];
__device__ int    g_off [N_CELL + 1];
__device__ int    g_cur [N_CELL];
__device__ int    g_bsum[64];
__device__ int    g_boff[64];
__device__ int    g_csr [E_EDGES];
__device__ __half g_y   [(size_t)N_GENE * DIM];   // fp16(x_gene @ Wl)
__device__ float  g_colsum[DIM];
__device__ float  g_colsq [DIM];

// ---------------- 0: zero counters/stats ----------------
__global__ void k_zero() {
    int i = blockIdx.x * blockDim.x + threadIdx.x;
    if (i < N_CELL) g_hist[i] = 0;
    if (i < DIM) { g_colsum[i] = 0.f; g_colsq[i] = 0.f; }
}

// ---------------- 1: histogram of edge destinations (x4 vectorized) ----------------
__global__ void k_hist(const int4* __restrict__ dst) {
    int i = blockIdx.x * blockDim.x + threadIdx.x;
    if (i < E_EDGES / 4) {
        int4 d = __ldg(&dst[i]);
        atomicAdd(&g_hist[d.x], 1);
        atomicAdd(&g_hist[d.y], 1);
        atomicAdd(&g_hist[d.z], 1);
        atomicAdd(&g_hist[d.w], 1);
    }
}

// ---------------- 2a: per-block inclusive scan ----------------
__global__ void k_scan1() {
    __shared__ int wsum[32];
    int t = threadIdx.x, lane = t & 31, wid = t >> 5;
    int i = blockIdx.x * 1024 + t;
    int v = (i < N_CELL) ? g_hist[i] : 0;
    int x = v;
    #pragma unroll
    for (int o = 1; o < 32; o <<= 1) {
        int y = __shfl_up_sync(0xffffffffu, x, o);
        if (lane >= o) x += y;
    }
    if (lane == 31) wsum[wid] = x;
    __syncthreads();
    if (wid == 0) {
        int w = wsum[lane];
        #pragma unroll
        for (int o = 1; o < 32; o <<= 1) {
            int y = __shfl_up_sync(0xffffffffu, w, o);
            if (lane >= o) w += y;
        }
        wsum[lane] = w;
    }
    __syncthreads();
    int incl = x + (wid ? wsum[wid - 1] : 0);
    if (i < N_CELL) g_cur[i] = incl;
    if (t == 1023) g_bsum[blockIdx.x] = incl;
}

// ---------------- 2b: scan the 59 block sums ----------------
__global__ void k_scan2() {
    int t = threadIdx.x, lane = t & 31, wid = t >> 5;  // 64 threads
    __shared__ int w0;
    int v = (t < SCAN_B) ? g_bsum[t] : 0;
    int x = v;
    #pragma unroll
    for (int o = 1; o < 32; o <<= 1) {
        int y = __shfl_up_sync(0xffffffffu, x, o);
        if (lane >= o) x += y;
    }
    if (t == 31) w0 = x;
    __syncthreads();
    int incl = x + (wid ? w0 : 0);
    if (t < SCAN_B) g_boff[t] = incl - v;
}

// ---------------- 2c: finalize offsets + write-cursors ----------------
__global__ void k_scan3() {
    int i = blockIdx.x * blockDim.x + threadIdx.x;
    if (i < N_CELL) {
        int incl = g_cur[i] + g_boff[i >> 10];
        g_off[i + 1] = incl;
        g_cur[i] = incl - g_hist[i];
        if (i == 0) g_off[0] = 0;
    }
}

// ---------------- 3: scatter edges into CSR (4 edges / thread for MLP) -------------
__global__ void k_scatter(const int4* __restrict__ src, const int4* __restrict__ dst) {
    int i = blockIdx.x * blockDim.x + threadIdx.x;
    if (i < E_EDGES / 4) {
        int4 s = __ldg(&src[i]);
        int4 d = __ldg(&dst[i]);
        int p0 = atomicAdd(&g_cur[d.x], 1);
        int p1 = atomicAdd(&g_cur[d.y], 1);
        int p2 = atomicAdd(&g_cur[d.z], 1);
        int p3 = atomicAdd(&g_cur[d.w], 1);
        g_csr[p0] = s.x;
        g_csr[p1] = s.y;
        g_csr[p2] = s.z;
        g_csr[p3] = s.w;
    }
}

// ---------------- 4: small fp32 GEMM  g_y = fp16(x_gene @ Wl) ----------------
__global__ __launch_bounds__(256) void k_ygemm(
    const float* __restrict__ A,
    const float* __restrict__ B,
    int M)
{
    __shared__ float As[32][132];
    __shared__ float Bs[32][128];

    int tid = threadIdx.x;
    int tr = tid >> 4, tc = tid & 15;
    int m0 = blockIdx.x * 128;

    float acc[8][8];
    #pragma unroll
    for (int r = 0; r < 8; r++)
        #pragma unroll
        for (int c = 0; c < 8; c++) acc[r][c] = 0.f;

    for (int k0 = 0; k0 < DIM; k0 += 32) {
        #pragma unroll
        for (int t = 0; t < 4; t++) {
            int idx = tid + t * 256;
            int row = idx >> 3, q = idx & 7;
            float4 v = {0.f, 0.f, 0.f, 0.f};
            int gm = m0 + row;
            if (gm < M) v = *(const float4*)&A[(size_t)gm * DIM + k0 + q * 4];
            As[q * 4 + 0][row] = v.x;
            As[q * 4 + 1][row] = v.y;
            As[q * 4 + 2][row] = v.z;
            As[q * 4 + 3][row] = v.w;
        }
        #pragma unroll
        for (int t = 0; t < 4; t++) {
            int idx = tid + t * 256;
            int bk = idx >> 5, bn4 = idx & 31;
            *(float4*)&Bs[bk][bn4 * 4] =
                *(const float4*)&B[(size_t)(k0 + bk) * DIM + bn4 * 4];
        }
        __syncthreads();
        #pragma unroll
        for (int kk = 0; kk < 32; kk++) {
            float a[8], b[8];
            *(float4*)&a[0] = *(const float4*)&As[kk][tr * 8];
            *(float4*)&a[4] = *(const float4*)&As[kk][tr * 8 + 4];
            *(float4*)&b[0] = *(const float4*)&Bs[kk][tc * 8];
            *(float4*)&b[4] = *(const float4*)&Bs[kk][tc * 8 + 4];
            #pragma unroll
            for (int r = 0; r < 8; r++)
                #pragma unroll
                for (int c = 0; c < 8; c++)
                    acc[r][c] += a[r] * b[c];
        }
        __syncthreads();
    }
    #pragma unroll
    for (int r = 0; r < 8; r++) {
        int gm = m0 + tr * 8 + r;
        if (gm < M) {
            #pragma unroll
            for (int c2 = 0; c2 < 4; c2++) {
                __half2 h = __floats2half2_rn(acc[r][c2 * 2], acc[r][c2 * 2 + 1]);
                *(__half2*)&g_y[(size_t)gm * DIM + tc * 8 + c2 * 2] = h;
            }
        }
    }
}

// ---------------- 5: tensor-core GEMM  out = x_cell @ Wr (direct store) -----------
__device__ __forceinline__ unsigned su32(const void* p) {
    return (unsigned)__cvta_generic_to_shared(p);
}
__device__ __forceinline__ void ldsm4(unsigned a, unsigned& r0, unsigned& r1,
                                      unsigned& r2, unsigned& r3) {
    asm volatile("ldmatrix.sync.aligned.m8n8.x4.shared.b16 {%0,%1,%2,%3}, [%4];"
                 : "=r"(r0), "=r"(r1), "=r"(r2), "=r"(r3) : "r"(a));
}
__device__ __forceinline__ void ldsm4t(unsigned a, unsigned& r0, unsigned& r1,
                                       unsigned& r2, unsigned& r3) {
    asm volatile("ldmatrix.sync.aligned.m8n8.x4.trans.shared.b16 {%0,%1,%2,%3}, [%4];"
                 : "=r"(r0), "=r"(r1), "=r"(r2), "=r"(r3) : "r"(a));
}
__device__ __forceinline__ void mma16816(float* d, const unsigned* a, const unsigned* b) {
    asm volatile(
        "mma.sync.aligned.m16n8k16.row.col.f32.f16.f16.f32 "
        "{%0,%1,%2,%3}, {%4,%5,%6,%7}, {%8,%9}, {%0,%1,%2,%3};"
        : "+f"(d[0]), "+f"(d[1]), "+f"(d[2]), "+f"(d[3])
        : "r"(a[0]), "r"(a[1]), "r"(a[2]), "r"(a[3]), "r"(b[0]), "r"(b[1]));
}

__global__ __launch_bounds__(256, 2) void k_gemm_direct(
    const float* __restrict__ x_cell,
    const float* __restrict__ Wr,
    float* __restrict__ out,
    int M)
{
    extern __shared__ char smem[];
    __half* As = (__half*)smem;                // [128][PADH]
    __half* Bs = (__half*)smem + 128 * PADH;   // [128][PADH], stored [k][n]

    int tid  = threadIdx.x;
    int warp = tid >> 5, lane = tid & 31;
    int wm = warp & 3, wn = warp >> 2;   // 4 x 2 warp grid; warp tile 32m x 64n
    int m0 = blockIdx.x * 128;

    // load A tile (fp32 -> fp16)
    #pragma unroll
    for (int it = 0; it < 16; it++) {
        int idx = tid + it * 256;
        int row = idx >> 5, q = idx & 31;
        float4 v = {0.f, 0.f, 0.f, 0.f};
        int gm = m0 + row;
        if (gm < M) v = *(const float4*)&x_cell[(size_t)gm * DIM + q * 4];
        *(__half2*)&As[row * PADH + q * 4]     = __floats2half2_rn(v.x, v.y);
        *(__half2*)&As[row * PADH + q * 4 + 2] = __floats2half2_rn(v.z, v.w);
    }
    // load B tile [k][n] (fp32 -> fp16)
    #pragma unroll
    for (int it = 0; it < 16; it++) {
        int idx = tid + it * 256;
        int k = idx >> 5, n4 = idx & 31;
        float4 v = *(const float4*)&Wr[(size_t)k * DIM + n4 * 4];
        *(__half2*)&Bs[k * PADH + n4 * 4]     = __floats2half2_rn(v.x, v.y);
        *(__half2*)&Bs[k * PADH + n4 * 4 + 2] = __floats2half2_rn(v.z, v.w);
    }
    __syncthreads();

    float acc[2][8][4];
    #pragma unroll
    for (int tm = 0; tm < 2; tm++)
        #pragma unroll
        for (int tn = 0; tn < 8; tn++)
            #pragma unroll
            for (int j = 0; j < 4; j++) acc[tm][tn][j] = 0.f;

    #pragma unroll
    for (int ks = 0; ks < 8; ks++) {
        unsigned a[2][4], b[8][2];
        #pragma unroll
        for (int tm = 0; tm < 2; tm++) {
            unsigned addr = su32(&As[(wm * 32 + tm * 16 + (lane & 15)) * PADH
                                     + ks * 16 + (lane >> 4) * 8]);
            ldsm4(addr, a[tm][0], a[tm][1], a[tm][2], a[tm][3]);
        }
        #pragma unroll
        for (int tp = 0; tp < 4; tp++) {
            unsigned addr = su32(&Bs[(ks * 16 + (lane & 15)) * PADH
                                     + wn * 64 + tp * 16 + (lane >> 4) * 8]);
            ldsm4t(addr, b[tp * 2][0], b[tp * 2][1], b[tp * 2 + 1][0], b[tp * 2 + 1][1]);
        }
        #pragma unroll
        for (int tm = 0; tm < 2; tm++)
            #pragma unroll
            for (int tn = 0; tn < 8; tn++)
                mma16816(acc[tm][tn], a[tm], b[tn]);
    }

    // direct fragment store to out (no epilogue work here)
    #pragma unroll
    for (int tm = 0; tm < 2; tm++) {
        int r0 = m0 + wm * 32 + tm * 16 + (lane >> 2);
        #pragma unroll
        for (int tn = 0; tn < 8; tn++) {
            int c = wn * 64 + tn * 8 + (lane & 3) * 2;
            if (r0 < M)
                *(float2*)&out[(size_t)r0 * DIM + c] =
                    make_float2(acc[tm][tn][0], acc[tm][tn][1]);
            if (r0 + 8 < M)
                *(float2*)&out[(size_t)(r0 + 8) * DIM + c] =
                    make_float2(acc[tm][tn][2], acc[tm][tn][3]);
        }
    }
}

// ---------------- 6: gather-mean + add into out + BN stats (high occupancy) --------
__global__ __launch_bounds__(256) void k_aggbn(float* __restrict__ out) {
    __shared__ float red[2][8][DIM];
    int tid  = threadIdx.x;
    int warp = tid >> 5, lane = tid & 31;
    const uint2* yv = (const uint2*)g_y;   // 4 halves per lane per gene row

    float s[4] = {0.f, 0.f, 0.f, 0.f};
    float q[4] = {0.f, 0.f, 0.f, 0.f};
    int cell0 = (blockIdx.x * 8 + warp) * CPW;

    for (int ci = 0; ci < CPW; ci++) {
        int gm = cell0 + ci;
        if (gm >= N_CELL) break;
        int es = g_off[gm], ee = g_off[gm + 1];

        float ax0=0.f, ax1=0.f, ax2=0.f, ax3=0.f;
        float bx0=0.f, bx1=0.f, bx2=0.f, bx3=0.f;
        float cx0=0.f, cx1=0.f, cx2=0.f, cx3=0.f;
        float dx0=0.f, dx1=0.f, dx2=0.f, dx3=0.f;
        int j = es;
        for (; j + 3 < ee; j += 4) {
            int g0 = __ldg(&g_csr[j]);
            int g1 = __ldg(&g_csr[j + 1]);
            int g2 = __ldg(&g_csr[j + 2]);
            int g3 = __ldg(&g_csr[j + 3]);
            uint2 u0 = __ldg(&yv[(size_t)g0 * 32 + lane]);
            uint2 u1 = __ldg(&yv[(size_t)g1 * 32 + lane]);
            uint2 u2 = __ldg(&yv[(size_t)g2 * 32 + lane]);
            uint2 u3 = __ldg(&yv[(size_t)g3 * 32 + lane]);
            float2 p0, q0;
            p0 = __half22float2(*(__half2*)&u0.x); q0 = __half22float2(*(__half2*)&u0.y);
            ax0 += p0.x; ax1 += p0.y; ax2 += q0.x; ax3 += q0.y;
            p0 = __half22float2(*(__half2*)&u1.x); q0 = __half22float2(*(__half2*)&u1.y);
            bx0 += p0.x; bx1 += p0.y; bx2 += q0.x; bx3 += q0.y;
            p0 = __half22float2(*(__half2*)&u2.x); q0 = __half22float2(*(__half2*)&u2.y);
            cx0 += p0.x; cx1 += p0.y; cx2 += q0.x; cx3 += q0.y;
            p0 = __half22float2(*(__half2*)&u3.x); q0 = __half22float2(*(__half2*)&u3.y);
            dx0 += p0.x; dx1 += p0.y; dx2 += q0.x; dx3 += q0.y;
        }
        for (; j < ee; j++) {
            int g0 = __ldg(&g_csr[j]);
            uint2 u0 = __ldg(&yv[(size_t)g0 * 32 + lane]);
            float2 p0 = __half22float2(*(__half2*)&u0.x);
            float2 q0 = __half22float2(*(__half2*)&u0.y);
            ax0 += p0.x; ax1 += p0.y; ax2 += q0.x; ax3 += q0.y;
        }
        float inv = 1.f / (float)max(ee - es, 1);
        float4 v = *(float4*)&out[(size_t)gm * DIM + lane * 4];
        v.x = fmaf(ax0 + bx0 + cx0 + dx0, inv, v.x);
        v.y = fmaf(ax1 + bx1 + cx1 + dx1, inv, v.y);
        v.z = fmaf(ax2 + bx2 + cx2 + dx2, inv, v.z);
        v.w = fmaf(ax3 + bx3 + cx3 + dx3, inv, v.w);
        *(float4*)&out[(size_t)gm * DIM + lane * 4] = v;
        s[0] += v.x; q[0] += v.x * v.x;
        s[1] += v.y; q[1] += v.y * v.y;
        s[2] += v.z; q[2] += v.z * v.z;
        s[3] += v.w; q[3] += v.w * v.w;
    }

    // block-reduce BN partials, one atomic per column per block
    #pragma unroll
    for (int c = 0; c < 4; c++) {
        red[0][warp][lane * 4 + c] = s[c];
        red[1][warp][lane * 4 + c] = q[c];
    }
    __syncthreads();
    if (tid < DIM) {
        float ss = 0.f, qq = 0.f;
        #pragma unroll
        for (int r = 0; r < 8; r++) { ss += red[0][r][tid]; qq += red[1][r][tid]; }
        atomicAdd(&g_colsum[tid], ss);
        atomicAdd(&g_colsq[tid], qq);
    }
}

// ---------------- 7: normalize in place (BN stats finalized inline) ----------------
__global__ void k_norm(float* __restrict__ out) {
    int i = blockIdx.x * blockDim.x + threadIdx.x;   // float4 index
    const int total = N_CELL * DIM / 4;
    if (i < total) {
        int c = (i & 31) * 4;
        const float invN = 1.f / (float)N_CELL;
        float mu0 = g_colsum[c + 0] * invN, mu1 = g_colsum[c + 1] * invN;
        float mu2 = g_colsum[c + 2] * invN, mu3 = g_colsum[c + 3] * invN;
        float rs0 = rsqrtf(g_colsq[c + 0] * invN - mu0 * mu0 + EPS_BN);
        float rs1 = rsqrtf(g_colsq[c + 1] * invN - mu1 * mu1 + EPS_BN);
        float rs2 = rsqrtf(g_colsq[c + 2] * invN - mu2 * mu2 + EPS_BN);
        float rs3 = rsqrtf(g_colsq[c + 3] * invN - mu3 * mu3 + EPS_BN);
        float4 v = ((float4*)out)[i];
        v.x = (v.x - mu0) * rs0;
        v.y = (v.y - mu1) * rs1;
        v.z = (v.z - mu2) * rs2;
        v.w = (v.w - mu3) * rs3;
        ((float4*)out)[i] = v;
    }
}

// ---------------- launch (two-stream fork/join inside graph capture) ----------------
extern "C" void kernel_launch(void* const* d_in, const int* in_sizes, int n_in,
                              void* d_out, int out_size) {
    const float* x_cell = (const float*)d_in[0];
    const float* x_gene = (const float*)d_in[1];
    const float* Wl_gc  = (const float*)d_in[2];
    const float* Wr_gc  = (const float*)d_in[4];
    const int* gc_src = (const int*)d_in[8];
    const int* gc_dst = (const int*)d_in[9];
    float* out = (float*)d_out;

    const float* Wl = Wl_gc + DIM * DIM;   // layer L-1 = 1
    const float* Wr = Wr_gc + DIM * DIM;

    static cudaStream_t sA = nullptr, sB = nullptr;
    static cudaEvent_t  e0 = nullptr, eB = nullptr, eA = nullptr;
    if (!sA) {
        cudaStreamCreateWithFlags(&sA, cudaStreamNonBlocking);
        cudaStreamCreateWithFlags(&sB, cudaStreamNonBlocking);
        cudaEventCreateWithFlags(&e0, cudaEventDisableTiming);
        cudaEventCreateWithFlags(&eB, cudaEventDisableTiming);
        cudaEventCreateWithFlags(&eA, cudaEventDisableTiming);
        cudaFuncSetAttribute(k_gemm_direct,
                             cudaFuncAttributeMaxDynamicSharedMemorySize, GEMM_SMEM);
    }

    // fork from the capture-origin (legacy) stream
    cudaEventRecord(e0, (cudaStream_t)0);
    cudaStreamWaitEvent(sA, e0, 0);
    cudaStreamWaitEvent(sB, e0, 0);

    // chain A: CSR build
    k_zero   <<<(N_CELL + 255) / 256, 256, 0, sA>>>();
    k_hist   <<<(E_EDGES / 4 + 255) / 256, 256, 0, sA>>>((const int4*)gc_dst);
    k_scan1  <<<SCAN_B, 1024, 0, sA>>>();
    k_scan2  <<<1, 64, 0, sA>>>();
    k_scan3  <<<(N_CELL + 255) / 256, 256, 0, sA>>>();
    k_scatter<<<(E_EDGES / 4 + 255) / 256, 256, 0, sA>>>(
        (const int4*)gc_src, (const int4*)gc_dst);

    // chain B: both GEMMs (independent of the graph structure)
    k_ygemm  <<<(N_GENE + 127) / 128, 256, 0, sB>>>(x_gene, Wl, N_GENE);
    k_gemm_direct<<<(N_CELL + 127) / 128, 256, GEMM_SMEM, sB>>>(x_cell, Wr, out, N_CELL);
    cudaEventRecord(eB, sB);

    // join: aggbn needs CSR (sA), g_y and out (sB)
    cudaStreamWaitEvent(sA, eB, 0);
    k_aggbn  <<<(N_CELL + 8 * CPW - 1) / (8 * CPW), 256, 0, sA>>>(out);
    k_norm   <<<(N_CELL * DIM / 4 + 255) / 256, 256, 0, sA>>>(out);

    // join back into the capture-origin stream
    cudaEventRecord(eA, sA);
    cudaStreamWaitEvent((cudaStream_t)0, eA, 0);
}

// round 9
// speedup vs baseline: 1.3382x; 1.0005x over previous
#include <cuda_runtime.h>
#include <cuda_fp16.h>

#define N_CELL  60000
#define N_GENE  4000
#define DIM     128
#define E_EDGES 1500000
#define EPS_BN  1e-5f
#define SCAN_B  ((N_CELL + 1023) / 1024)   // 59

#define PADH 136   // half stride for As/Bs (17*8: ldmatrix-aligned)
#define GEMM_SMEM (2 * 128 * PADH * 2)     // As+Bs fp16

#define CPW 8      // cells per warp in k_aggbn

// ---------------- scratch (static __device__, no allocation) ----------------
__device__ int    g_hist[N_CELL];
__device__ int    g_off [N_CELL + 1];
__device__ int    g_cur [N_CELL];
__device__ int    g_pub [64];              // decoupled-lookback: (aggregate+1) or 0
__device__ int    g_csr [E_EDGES];
__device__ __half g_y   [(size_t)N_GENE * DIM];   // fp16(x_gene @ Wl)
__device__ float  g_colsum[DIM];
__device__ float  g_colsq [DIM];

// ---------------- 0: zero counters/stats/flags ----------------
__global__ void k_zero() {
    int i = blockIdx.x * blockDim.x + threadIdx.x;
    if (i < N_CELL) g_hist[i] = 0;
    if (i < DIM) { g_colsum[i] = 0.f; g_colsq[i] = 0.f; }
    if (i < 64) g_pub[i] = 0;
}

// ---------------- 1: histogram of edge destinations (x4 vectorized) ----------------
__global__ void k_hist(const int4* __restrict__ dst) {
    int i = blockIdx.x * blockDim.x + threadIdx.x;
    if (i < E_EDGES / 4) {
        int4 d = __ldg(&dst[i]);
        atomicAdd(&g_hist[d.x], 1);
        atomicAdd(&g_hist[d.y], 1);
        atomicAdd(&g_hist[d.z], 1);
        atomicAdd(&g_hist[d.w], 1);
    }
}

// ---------------- 2: single-kernel decoupled-lookback scan ----------------
// Produces g_off (exclusive CSR offsets) and g_cur (scatter cursors).
__global__ void k_scanall() {
    __shared__ int wsum[32];
    __shared__ int exc;
    int b = blockIdx.x;
    int t = threadIdx.x, lane = t & 31, wid = t >> 5;
    if (t == 0) exc = 0;
    int i = b * 1024 + t;
    int v = (i < N_CELL) ? g_hist[i] : 0;
    int x = v;
    #pragma unroll
    for (int o = 1; o < 32; o <<= 1) {
        int y = __shfl_up_sync(0xffffffffu, x, o);
        if (lane >= o) x += y;
    }
    if (lane == 31) wsum[wid] = x;
    __syncthreads();
    if (wid == 0) {
        int w = wsum[lane];
        #pragma unroll
        for (int o = 1; o < 32; o <<= 1) {
            int y = __shfl_up_sync(0xffffffffu, w, o);
            if (lane >= o) w += y;
        }
        wsum[lane] = w;
    }
    __syncthreads();
    int incl = x + (wid ? wsum[wid - 1] : 0);

    // publish block aggregate (value+1 so 0 means "not ready")
    if (t == 1023) atomicExch(&g_pub[b], incl + 1);

    // lookback: sum all predecessor aggregates (max 58 polls, lane-parallel)
    if (t < b) {
        int p;
        do { p = atomicAdd(&g_pub[t], 0); } while (p == 0);
        atomicAdd(&exc, p - 1);
    }
    __syncthreads();
    int off = exc;
    if (i < N_CELL) {
        int gi = incl + off;
        g_off[i + 1] = gi;
        g_cur[i] = gi - v;
        if (i == 0) g_off[0] = 0;
    }
}

// ---------------- 3: scatter edges into CSR (4 edges / thread for MLP) -------------
__global__ void k_scatter(const int4* __restrict__ src, const int4* __restrict__ dst) {
    int i = blockIdx.x * blockDim.x + threadIdx.x;
    if (i < E_EDGES / 4) {
        int4 s = __ldg(&src[i]);
        int4 d = __ldg(&dst[i]);
        int p0 = atomicAdd(&g_cur[d.x], 1);
        int p1 = atomicAdd(&g_cur[d.y], 1);
        int p2 = atomicAdd(&g_cur[d.z], 1);
        int p3 = atomicAdd(&g_cur[d.w], 1);
        g_csr[p0] = s.x;
        g_csr[p1] = s.y;
        g_csr[p2] = s.z;
        g_csr[p3] = s.w;
    }
}

// ---------------- 4: small fp32 GEMM  g_y = fp16(x_gene @ Wl) ----------------
__global__ __launch_bounds__(256) void k_ygemm(
    const float* __restrict__ A,
    const float* __restrict__ B,
    int M)
{
    __shared__ float As[32][132];
    __shared__ float Bs[32][128];

    int tid = threadIdx.x;
    int tr = tid >> 4, tc = tid & 15;
    int m0 = blockIdx.x * 128;

    float acc[8][8];
    #pragma unroll
    for (int r = 0; r < 8; r++)
        #pragma unroll
        for (int c = 0; c < 8; c++) acc[r][c] = 0.f;

    for (int k0 = 0; k0 < DIM; k0 += 32) {
        #pragma unroll
        for (int t = 0; t < 4; t++) {
            int idx = tid + t * 256;
            int row = idx >> 3, q = idx & 7;
            float4 v = {0.f, 0.f, 0.f, 0.f};
            int gm = m0 + row;
            if (gm < M) v = *(const float4*)&A[(size_t)gm * DIM + k0 + q * 4];
            As[q * 4 + 0][row] = v.x;
            As[q * 4 + 1][row] = v.y;
            As[q * 4 + 2][row] = v.z;
            As[q * 4 + 3][row] = v.w;
        }
        #pragma unroll
        for (int t = 0; t < 4; t++) {
            int idx = tid + t * 256;
            int bk = idx >> 5, bn4 = idx & 31;
            *(float4*)&Bs[bk][bn4 * 4] =
                *(const float4*)&B[(size_t)(k0 + bk) * DIM + bn4 * 4];
        }
        __syncthreads();
        #pragma unroll
        for (int kk = 0; kk < 32; kk++) {
            float a[8], b[8];
            *(float4*)&a[0] = *(const float4*)&As[kk][tr * 8];
            *(float4*)&a[4] = *(const float4*)&As[kk][tr * 8 + 4];
            *(float4*)&b[0] = *(const float4*)&Bs[kk][tc * 8];
            *(float4*)&b[4] = *(const float4*)&Bs[kk][tc * 8 + 4];
            #pragma unroll
            for (int r = 0; r < 8; r++)
                #pragma unroll
                for (int c = 0; c < 8; c++)
                    acc[r][c] += a[r] * b[c];
        }
        __syncthreads();
    }
    #pragma unroll
    for (int r = 0; r < 8; r++) {
        int gm = m0 + tr * 8 + r;
        if (gm < M) {
            #pragma unroll
            for (int c2 = 0; c2 < 4; c2++) {
                __half2 h = __floats2half2_rn(acc[r][c2 * 2], acc[r][c2 * 2 + 1]);
                *(__half2*)&g_y[(size_t)gm * DIM + tc * 8 + c2 * 2] = h;
            }
        }
    }
}

// ---------------- 5: tensor-core GEMM  out = x_cell @ Wr (direct store) -----------
__device__ __forceinline__ unsigned su32(const void* p) {
    return (unsigned)__cvta_generic_to_shared(p);
}
__device__ __forceinline__ void ldsm4(unsigned a, unsigned& r0, unsigned& r1,
                                      unsigned& r2, unsigned& r3) {
    asm volatile("ldmatrix.sync.aligned.m8n8.x4.shared.b16 {%0,%1,%2,%3}, [%4];"
                 : "=r"(r0), "=r"(r1), "=r"(r2), "=r"(r3) : "r"(a));
}
__device__ __forceinline__ void ldsm4t(unsigned a, unsigned& r0, unsigned& r1,
                                       unsigned& r2, unsigned& r3) {
    asm volatile("ldmatrix.sync.aligned.m8n8.x4.trans.shared.b16 {%0,%1,%2,%3}, [%4];"
                 : "=r"(r0), "=r"(r1), "=r"(r2), "=r"(r3) : "r"(a));
}
__device__ __forceinline__ void mma16816(float* d, const unsigned* a, const unsigned* b) {
    asm volatile(
        "mma.sync.aligned.m16n8k16.row.col.f32.f16.f16.f32 "
        "{%0,%1,%2,%3}, {%4,%5,%6,%7}, {%8,%9}, {%0,%1,%2,%3};"
        : "+f"(d[0]), "+f"(d[1]), "+f"(d[2]), "+f"(d[3])
        : "r"(a[0]), "r"(a[1]), "r"(a[2]), "r"(a[3]), "r"(b[0]), "r"(b[1]));
}

__global__ __launch_bounds__(256, 2) void k_gemm_direct(
    const float* __restrict__ x_cell,
    const float* __restrict__ Wr,
    float* __restrict__ out,
    int M)
{
    extern __shared__ char smem[];
    __half* As = (__half*)smem;                // [128][PADH]
    __half* Bs = (__half*)smem + 128 * PADH;   // [128][PADH], stored [k][n]

    int tid  = threadIdx.x;
    int warp = tid >> 5, lane = tid & 31;
    int wm = warp & 3, wn = warp >> 2;   // 4 x 2 warp grid; warp tile 32m x 64n
    int m0 = blockIdx.x * 128;

    // load A tile (fp32 -> fp16)
    #pragma unroll
    for (int it = 0; it < 16; it++) {
        int idx = tid + it * 256;
        int row = idx >> 5, q = idx & 31;
        float4 v = {0.f, 0.f, 0.f, 0.f};
        int gm = m0 + row;
        if (gm < M) v = *(const float4*)&x_cell[(size_t)gm * DIM + q * 4];
        *(__half2*)&As[row * PADH + q * 4]     = __floats2half2_rn(v.x, v.y);
        *(__half2*)&As[row * PADH + q * 4 + 2] = __floats2half2_rn(v.z, v.w);
    }
    // load B tile [k][n] (fp32 -> fp16)
    #pragma unroll
    for (int it = 0; it < 16; it++) {
        int idx = tid + it * 256;
        int k = idx >> 5, n4 = idx & 31;
        float4 v = *(const float4*)&Wr[(size_t)k * DIM + n4 * 4];
        *(__half2*)&Bs[k * PADH + n4 * 4]     = __floats2half2_rn(v.x, v.y);
        *(__half2*)&Bs[k * PADH + n4 * 4 + 2] = __floats2half2_rn(v.z, v.w);
    }
    __syncthreads();

    float acc[2][8][4];
    #pragma unroll
    for (int tm = 0; tm < 2; tm++)
        #pragma unroll
        for (int tn = 0; tn < 8; tn++)
            #pragma unroll
            for (int j = 0; j < 4; j++) acc[tm][tn][j] = 0.f;

    #pragma unroll
    for (int ks = 0; ks < 8; ks++) {
        unsigned a[2][4], b[8][2];
        #pragma unroll
        for (int tm = 0; tm < 2; tm++) {
            unsigned addr = su32(&As[(wm * 32 + tm * 16 + (lane & 15)) * PADH
                                     + ks * 16 + (lane >> 4) * 8]);
            ldsm4(addr, a[tm][0], a[tm][1], a[tm][2], a[tm][3]);
        }
        #pragma unroll
        for (int tp = 0; tp < 4; tp++) {
            unsigned addr = su32(&Bs[(ks * 16 + (lane & 15)) * PADH
                                     + wn * 64 + tp * 16 + (lane >> 4) * 8]);
            ldsm4t(addr, b[tp * 2][0], b[tp * 2][1], b[tp * 2 + 1][0], b[tp * 2 + 1][1]);
        }
        #pragma unroll
        for (int tm = 0; tm < 2; tm++)
            #pragma unroll
            for (int tn = 0; tn < 8; tn++)
                mma16816(acc[tm][tn], a[tm], b[tn]);
    }

    // direct fragment store to out (no epilogue work here)
    #pragma unroll
    for (int tm = 0; tm < 2; tm++) {
        int r0 = m0 + wm * 32 + tm * 16 + (lane >> 2);
        #pragma unroll
        for (int tn = 0; tn < 8; tn++) {
            int c = wn * 64 + tn * 8 + (lane & 3) * 2;
            if (r0 < M)
                *(float2*)&out[(size_t)r0 * DIM + c] =
                    make_float2(acc[tm][tn][0], acc[tm][tn][1]);
            if (r0 + 8 < M)
                *(float2*)&out[(size_t)(r0 + 8) * DIM + c] =
                    make_float2(acc[tm][tn][2], acc[tm][tn][3]);
        }
    }
}

// ---------------- 6: gather-mean + add into out + BN stats (high occupancy) --------
__global__ __launch_bounds__(256) void k_aggbn(float* __restrict__ out) {
    __shared__ float red[2][8][DIM];
    int tid  = threadIdx.x;
    int warp = tid >> 5, lane = tid & 31;
    const uint2* yv = (const uint2*)g_y;   // 4 halves per lane per gene row

    float s[4] = {0.f, 0.f, 0.f, 0.f};
    float q[4] = {0.f, 0.f, 0.f, 0.f};
    int cell0 = (blockIdx.x * 8 + warp) * CPW;

    for (int ci = 0; ci < CPW; ci++) {
        int gm = cell0 + ci;
        if (gm >= N_CELL) break;
        int es = g_off[gm], ee = g_off[gm + 1];

        float ax0=0.f, ax1=0.f, ax2=0.f, ax3=0.f;
        float bx0=0.f, bx1=0.f, bx2=0.f, bx3=0.f;
        float cx0=0.f, cx1=0.f, cx2=0.f, cx3=0.f;
        float dx0=0.f, dx1=0.f, dx2=0.f, dx3=0.f;
        int j = es;
        for (; j + 3 < ee; j += 4) {
            int g0 = __ldg(&g_csr[j]);
            int g1 = __ldg(&g_csr[j + 1]);
            int g2 = __ldg(&g_csr[j + 2]);
            int g3 = __ldg(&g_csr[j + 3]);
            uint2 u0 = __ldg(&yv[(size_t)g0 * 32 + lane]);
            uint2 u1 = __ldg(&yv[(size_t)g1 * 32 + lane]);
            uint2 u2 = __ldg(&yv[(size_t)g2 * 32 + lane]);
            uint2 u3 = __ldg(&yv[(size_t)g3 * 32 + lane]);
            float2 p0, q0;
            p0 = __half22float2(*(__half2*)&u0.x); q0 = __half22float2(*(__half2*)&u0.y);
            ax0 += p0.x; ax1 += p0.y; ax2 += q0.x; ax3 += q0.y;
            p0 = __half22float2(*(__half2*)&u1.x); q0 = __half22float2(*(__half2*)&u1.y);
            bx0 += p0.x; bx1 += p0.y; bx2 += q0.x; bx3 += q0.y;
            p0 = __half22float2(*(__half2*)&u2.x); q0 = __half22float2(*(__half2*)&u2.y);
            cx0 += p0.x; cx1 += p0.y; cx2 += q0.x; cx3 += q0.y;
            p0 = __half22float2(*(__half2*)&u3.x); q0 = __half22float2(*(__half2*)&u3.y);
            dx0 += p0.x; dx1 += p0.y; dx2 += q0.x; dx3 += q0.y;
        }
        for (; j < ee; j++) {
            int g0 = __ldg(&g_csr[j]);
            uint2 u0 = __ldg(&yv[(size_t)g0 * 32 + lane]);
            float2 p0 = __half22float2(*(__half2*)&u0.x);
            float2 q0 = __half22float2(*(__half2*)&u0.y);
            ax0 += p0.x; ax1 += p0.y; ax2 += q0.x; ax3 += q0.y;
        }
        float inv = 1.f / (float)max(ee - es, 1);
        float4 v = *(float4*)&out[(size_t)gm * DIM + lane * 4];
        v.x = fmaf(ax0 + bx0 + cx0 + dx0, inv, v.x);
        v.y = fmaf(ax1 + bx1 + cx1 + dx1, inv, v.y);
        v.z = fmaf(ax2 + bx2 + cx2 + dx2, inv, v.z);
        v.w = fmaf(ax3 + bx3 + cx3 + dx3, inv, v.w);
        *(float4*)&out[(size_t)gm * DIM + lane * 4] = v;
        s[0] += v.x; q[0] += v.x * v.x;
        s[1] += v.y; q[1] += v.y * v.y;
        s[2] += v.z; q[2] += v.z * v.z;
        s[3] += v.w; q[3] += v.w * v.w;
    }

    // block-reduce BN partials, one atomic per column per block
    #pragma unroll
    for (int c = 0; c < 4; c++) {
        red[0][warp][lane * 4 + c] = s[c];
        red[1][warp][lane * 4 + c] = q[c];
    }
    __syncthreads();
    if (tid < DIM) {
        float ss = 0.f, qq = 0.f;
        #pragma unroll
        for (int r = 0; r < 8; r++) { ss += red[0][r][tid]; qq += red[1][r][tid]; }
        atomicAdd(&g_colsum[tid], ss);
        atomicAdd(&g_colsq[tid], qq);
    }
}

// ---------------- 7: normalize in place (BN stats finalized inline) ----------------
__global__ void k_norm(float* __restrict__ out) {
    int i = blockIdx.x * blockDim.x + threadIdx.x;   // float4 index
    const int total = N_CELL * DIM / 4;
    if (i < total) {
        int c = (i & 31) * 4;
        const float invN = 1.f / (float)N_CELL;
        float mu0 = g_colsum[c + 0] * invN, mu1 = g_colsum[c + 1] * invN;
        float mu2 = g_colsum[c + 2] * invN, mu3 = g_colsum[c + 3] * invN;
        float rs0 = rsqrtf(g_colsq[c + 0] * invN - mu0 * mu0 + EPS_BN);
        float rs1 = rsqrtf(g_colsq[c + 1] * invN - mu1 * mu1 + EPS_BN);
        float rs2 = rsqrtf(g_colsq[c + 2] * invN - mu2 * mu2 + EPS_BN);
        float rs3 = rsqrtf(g_colsq[c + 3] * invN - mu3 * mu3 + EPS_BN);
        float4 v = ((float4*)out)[i];
        v.x = (v.x - mu0) * rs0;
        v.y = (v.y - mu1) * rs1;
        v.z = (v.z - mu2) * rs2;
        v.w = (v.w - mu3) * rs3;
        ((float4*)out)[i] = v;
    }
}

// ---------------- launch (two-stream fork/join inside graph capture) ----------------
extern "C" void kernel_launch(void* const* d_in, const int* in_sizes, int n_in,
                              void* d_out, int out_size) {
    const float* x_cell = (const float*)d_in[0];
    const float* x_gene = (const float*)d_in[1];
    const float* Wl_gc  = (const float*)d_in[2];
    const float* Wr_gc  = (const float*)d_in[4];
    const int* gc_src = (const int*)d_in[8];
    const int* gc_dst = (const int*)d_in[9];
    float* out = (float*)d_out;

    const float* Wl = Wl_gc + DIM * DIM;   // layer L-1 = 1
    const float* Wr = Wr_gc + DIM * DIM;

    static cudaStream_t sA = nullptr, sB = nullptr;
    static cudaEvent_t  e0 = nullptr, eB = nullptr, eA = nullptr;
    if (!sA) {
        cudaStreamCreateWithFlags(&sA, cudaStreamNonBlocking);
        cudaStreamCreateWithFlags(&sB, cudaStreamNonBlocking);
        cudaEventCreateWithFlags(&e0, cudaEventDisableTiming);
        cudaEventCreateWithFlags(&eB, cudaEventDisableTiming);
        cudaEventCreateWithFlags(&eA, cudaEventDisableTiming);
        cudaFuncSetAttribute(k_gemm_direct,
                             cudaFuncAttributeMaxDynamicSharedMemorySize, GEMM_SMEM);
    }

    // fork from the capture-origin (legacy) stream
    cudaEventRecord(e0, (cudaStream_t)0);
    cudaStreamWaitEvent(sA, e0, 0);
    cudaStreamWaitEvent(sB, e0, 0);

    // chain A: CSR build
    k_zero   <<<(N_CELL + 255) / 256, 256, 0, sA>>>();
    k_hist   <<<(E_EDGES / 4 + 255) / 256, 256, 0, sA>>>((const int4*)gc_dst);
    k_scanall<<<SCAN_B, 1024, 0, sA>>>();
    k_scatter<<<(E_EDGES / 4 + 255) / 256, 256, 0, sA>>>(
        (const int4*)gc_src, (const int4*)gc_dst);

    // chain B: both GEMMs (independent of the graph structure)
    k_ygemm  <<<(N_GENE + 127) / 128, 256, 0, sB>>>(x_gene, Wl, N_GENE);
    k_gemm_direct<<<(N_CELL + 127) / 128, 256, GEMM_SMEM, sB>>>(x_cell, Wr, out, N_CELL);
    cudaEventRecord(eB, sB);

    // join: aggbn needs CSR (sA), g_y and out (sB)
    cudaStreamWaitEvent(sA, eB, 0);
    k_aggbn  <<<(N_CELL + 8 * CPW - 1) / (8 * CPW), 256, 0, sA>>>(out);
    k_norm   <<<(N_CELL * DIM / 4 + 255) / 256, 256, 0, sA>>>(out);

    // join back into the capture-origin stream
    cudaEventRecord(eA, sA);
    cudaStreamWaitEvent((cudaStream_t)0, eA, 0);
}